// round 5
// baseline (speedup 1.0000x reference)
#include <cuda_runtime.h>
#include <cstdint>
#include <math.h>

// ---------------- constants -----------------
#define H 512
#define W 512
#define B 8
#define NPIX (B*H*W)          // 2097152

__constant__ float cw1[64*64];
__constant__ float cb1[64];
__constant__ float cw2[64*32];
__constant__ float cb2[32];
__constant__ float cwrgb[32*3];
__constant__ float cbrgb[3];
__constant__ float cwvel[32*2];
__constant__ float cbvel[2];
__constant__ float cwhid[32*8];
__constant__ float cbhid[8];

// scratch (static device memory: allowed; no allocation)
__device__ float g_vxn[NPIX];
__device__ float g_vyn[NPIX];
__device__ float g_m0[NPIX];
__device__ float g_m1[NPIX];
__device__ unsigned int g_keys[6]; // K0,K1, k1n0,k1n1, k2n0,k2n1

// ---------------- threefry2x32 (bit-exact JAX) -----------------
__device__ __forceinline__ uint32_t rotl32(uint32_t v, int r){ return (v<<r)|(v>>(32-r)); }

__device__ __forceinline__ void tf2x32(uint32_t k0, uint32_t k1, uint32_t x0, uint32_t x1,
                                       uint32_t& o0, uint32_t& o1){
    uint32_t k2 = k0 ^ k1 ^ 0x1BD11BDAu;
    x0 += k0; x1 += k1;
#define TFR(r) { x0 += x1; x1 = rotl32(x1,(r)); x1 ^= x0; }
    TFR(13) TFR(15) TFR(26) TFR(6)   x0 += k1; x1 += k2 + 1u;
    TFR(17) TFR(29) TFR(16) TFR(24)  x0 += k2; x1 += k0 + 2u;
    TFR(13) TFR(15) TFR(26) TFR(6)   x0 += k0; x1 += k1 + 3u;
    TFR(17) TFR(29) TFR(16) TFR(24)  x0 += k1; x1 += k2 + 4u;
    TFR(13) TFR(15) TFR(26) TFR(6)   x0 += k2; x1 += k0 + 5u;
#undef TFR
    o0 = x0; o1 = x1;
}

// PARTITIONABLE threefry random_bits (jax_threefry_partitionable=True):
// element i uses 64-bit counter i -> (hi, lo) = (0, i);
// 32-bit output = bits1 ^ bits2  (XOR fold of both threefry outputs).
__device__ __forceinline__ uint32_t rng_bits(uint32_t k0, uint32_t k1, uint32_t i){
    uint32_t o0, o1;
    tf2x32(k0, k1, 0u, i, o0, o1);
    return o0 ^ o1;
}

__device__ __forceinline__ float bits_to_u01(uint32_t b){
    return __uint_as_float((b >> 9) | 0x3f800000u) - 1.0f;
}

// XLA ErfInv (f32, Giles polynomial)
__device__ __forceinline__ float erfinv32(float x){
    float w = -log1pf(-x*x);
    float p;
    if (w < 5.0f){
        w -= 2.5f;
        p = 2.81022636e-08f;
        p = fmaf(p, w, 3.43273939e-07f);
        p = fmaf(p, w, -3.5233877e-06f);
        p = fmaf(p, w, -4.39150654e-06f);
        p = fmaf(p, w, 0.00021858087f);
        p = fmaf(p, w, -0.00125372503f);
        p = fmaf(p, w, -0.00417768164f);
        p = fmaf(p, w, 0.246640727f);
        p = fmaf(p, w, 1.50140941f);
    } else {
        w = sqrtf(w) - 3.0f;
        p = -0.000200214257f;
        p = fmaf(p, w, 0.000100950558f);
        p = fmaf(p, w, 0.00134934322f);
        p = fmaf(p, w, -0.00367342844f);
        p = fmaf(p, w, 0.00573950773f);
        p = fmaf(p, w, -0.0076224613f);
        p = fmaf(p, w, 0.00943887047f);
        p = fmaf(p, w, 1.00167406f);
        p = fmaf(p, w, 2.83297682f);
    }
    return p * x;
}

// ---------------- key derivation: fold-like split chain (partitionable mode) ----------------
__global__ void key_setup(const int* __restrict__ seed){
    uint32_t K0 = 0u;
    uint32_t K1 = (uint32_t)(*seed);
    // split(key, 2) fold-like: subkey j = full output pair of tf(key, (0, j))
    // key, nk = split(key)  -> nk = tf(K, (0,1))
    uint32_t nk0, nk1;
    tf2x32(K0, K1, 0u, 1u, nk0, nk1);
    // k1, k2 = split(nk) -> k1 = tf(nk,(0,0)), k2 = tf(nk,(0,1))
    uint32_t a0,a1,b0,b1;
    tf2x32(nk0, nk1, 0u, 0u, a0, a1);
    tf2x32(nk0, nk1, 0u, 1u, b0, b1);
    g_keys[0] = K0; g_keys[1] = K1;
    g_keys[2] = a0; g_keys[3] = a1;   // k1 (vx noise)
    g_keys[4] = b0; g_keys[5] = b1;   // k2 (vy noise)
}

// ---------------- main NCA kernel ----------------
__global__ __launch_bounds__(128)
void nca_kernel(const float* __restrict__ S, float* __restrict__ O){
    __shared__ float sb[64*128];   // activation spill: column-major, conflict-free
    const int tid = threadIdx.x;
    const int i   = blockIdx.x * 128 + tid;
    const int x   = i & (W-1);
    const int y   = (i >> 9) & (H-1);
    const int b   = i >> 18;

    const int xm = (x-1)&(W-1), xp = (x+1)&(W-1);
    const int ym = (y-1)&(H-1), yp = (y+1)&(H-1);
    const size_t rowb = ((size_t)b) << 18;
    const float4* S4 = (const float4*)S;

#define PIXF4(yy,xx) ((rowb + (((size_t)(yy))<<9) + (size_t)(xx)) * 4)

    float p[64];
    {   // center: s + lap(-4s)
        size_t a = PIXF4(y,x);
#pragma unroll
        for (int q = 0; q < 4; q++){
            float4 v = __ldg(&S4[a+q]);
            p[4*q+0]=v.x; p[4*q+1]=v.y; p[4*q+2]=v.z; p[4*q+3]=v.w;
        }
#pragma unroll
        for (int c = 0; c < 16; c++){ p[16+c]=0.f; p[32+c]=0.f; p[48+c]=-4.0f*p[c]; }
    }

#define NBR(yy,xx,STMT) { size_t a = PIXF4(yy,xx); \
    _Pragma("unroll") for (int q = 0; q < 4; q++){ \
        float4 vv = __ldg(&S4[a+q]); \
        float varr[4] = {vv.x, vv.y, vv.z, vv.w}; \
        _Pragma("unroll") for (int j = 0; j < 4; j++){ \
            int c = 4*q+j; float v = varr[j]; STMT; } } }

    // coefficients: gx -> p[16+c], gy -> p[32+c], lap -> p[48+c]
    NBR(ym, xm, { p[16+c] -= v; p[32+c] -= v; })
    NBR(ym, x , { p[32+c] = fmaf(-2.0f, v, p[32+c]); p[48+c] += v; })
    NBR(ym, xp, { p[16+c] += v; p[32+c] -= v; })
    NBR(y , xm, { p[16+c] = fmaf(-2.0f, v, p[16+c]); p[48+c] += v; })
    NBR(y , xp, { p[16+c] = fmaf( 2.0f, v, p[16+c]); p[48+c] += v; })
    NBR(yp, xm, { p[16+c] -= v; p[32+c] += v; })
    NBR(yp, x , { p[32+c] = fmaf( 2.0f, v, p[32+c]); p[48+c] += v; })
    NBR(yp, xp, { p[16+c] += v; p[32+c] += v; })
#undef NBR

#pragma unroll
    for (int c = 0; c < 16; c++){
        p[16+c] *= 0.125f;  // /8
        p[32+c] *= 0.125f;  // /8
        p[48+c] *= 0.25f;   // /4
    }

    // spill p to smem (own column; no cross-thread use -> no barriers)
#pragma unroll
    for (int c = 0; c < 64; c++) sb[c*128 + tid] = p[c];

    // ---- layer 1: h[64] = relu(p . w1 + b1) ----
    float h[64];
#pragma unroll
    for (int d = 0; d < 64; d++) h[d] = cb1[d];
#pragma unroll 4
    for (int c = 0; c < 64; c++){
        float pc = sb[c*128 + tid];
        const float4* wrow = (const float4*)(cw1 + c*64);
#pragma unroll
        for (int d4 = 0; d4 < 16; d4++){
            float4 wv = wrow[d4];
            h[4*d4+0] = fmaf(pc, wv.x, h[4*d4+0]);
            h[4*d4+1] = fmaf(pc, wv.y, h[4*d4+1]);
            h[4*d4+2] = fmaf(pc, wv.z, h[4*d4+2]);
            h[4*d4+3] = fmaf(pc, wv.w, h[4*d4+3]);
        }
    }
#pragma unroll
    for (int d = 0; d < 64; d++){ h[d] = fmaxf(h[d], 0.0f); sb[d*128 + tid] = h[d]; }

    // ---- layer 2: xo[32] = relu(h . w2 + b2) ----
    float xo[32];
#pragma unroll
    for (int d = 0; d < 32; d++) xo[d] = cb2[d];
#pragma unroll 4
    for (int c = 0; c < 64; c++){
        float hc = sb[c*128 + tid];
        const float4* wrow = (const float4*)(cw2 + c*32);
#pragma unroll
        for (int d4 = 0; d4 < 8; d4++){
            float4 wv = wrow[d4];
            xo[4*d4+0] = fmaf(hc, wv.x, xo[4*d4+0]);
            xo[4*d4+1] = fmaf(hc, wv.y, xo[4*d4+1]);
            xo[4*d4+2] = fmaf(hc, wv.z, xo[4*d4+2]);
            xo[4*d4+3] = fmaf(hc, wv.w, xo[4*d4+3]);
        }
    }
#pragma unroll
    for (int d = 0; d < 32; d++) xo[d] = fmaxf(xo[d], 0.0f);

    // ---- heads ----
    float r0 = cbrgb[0], r1 = cbrgb[1], r2 = cbrgb[2];
    float dvx = cbvel[0], dvy = cbvel[1];
    float hid[8];
#pragma unroll
    for (int j = 0; j < 8; j++) hid[j] = cbhid[j];
#pragma unroll
    for (int c = 0; c < 32; c++){
        float xc = xo[c];
        r0  = fmaf(xc, cwrgb[c*3+0], r0);
        r1  = fmaf(xc, cwrgb[c*3+1], r1);
        r2  = fmaf(xc, cwrgb[c*3+2], r2);
        dvx = fmaf(xc, cwvel[c*2+0], dvx);
        dvy = fmaf(xc, cwvel[c*2+1], dvy);
#pragma unroll
        for (int j = 0; j < 8; j++) hid[j] = fmaf(xc, cwhid[c*8+j], hid[j]);
    }

    // ---- RNG: fire mask + velocity noise (partitionable threefry, XOR fold) ----
    uint32_t K0 = g_keys[0], K1 = g_keys[1];
    uint32_t A0 = g_keys[2], A1 = g_keys[3];
    uint32_t B0 = g_keys[4], B1 = g_keys[5];
    uint32_t ui = (uint32_t)i;

    float um = bits_to_u01(rng_bits(K0, K1, ui));
    float m  = (um < 0.5f) ? 1.0f : 0.0f;

    const float LO   = -0.99999994f;     // nextafter(-1, 0) in f32
    const float SPAN =  1.99999994f;     // 1.0f - LO, computed in f32
    float uxr = bits_to_u01(rng_bits(A0, A1, ui));
    float uyr = bits_to_u01(rng_bits(B0, B1, ui));
    float ux  = fmaxf(LO, uxr * SPAN + LO);
    float uy  = fmaxf(LO, uyr * SPAN + LO);
    float zx  = 1.41421356f * erfinv32(ux);
    float zy  = 1.41421356f * erfinv32(uy);

    // ---- state update ----
    float o0c = fminf(fmaxf(p[0] + r0*m, 0.0f), 1.0f);
    float o1c = fminf(fmaxf(p[1] + r1*m, 0.0f), 1.0f);
    float o2c = fminf(fmaxf(p[2] + r2*m, 0.0f), 1.0f);
    float vx  = 0.95f * fminf(fmaxf(p[4] + dvx*m, -1.0f), 1.0f);
    float vy  = 0.95f * fminf(fmaxf(p[5] + dvy*m, -1.0f), 1.0f);

    float4* O4 = (float4*)O;
    size_t ob = (size_t)i * 4;
    O4[ob+0] = make_float4(o0c, o1c, o2c, p[3]);  // ch3 overwritten by diffuse pass
    O4[ob+1] = make_float4(vx, vy, p[6], p[7]);
    O4[ob+2] = make_float4(p[8]  + hid[0]*m, p[9]  + hid[1]*m,
                           p[10] + hid[2]*m, p[11] + hid[3]*m);
    O4[ob+3] = make_float4(p[12] + hid[4]*m, p[13] + hid[5]*m,
                           p[14] + hid[6]*m, p[15] + hid[7]*m);

    g_vxn[i] = vx + 0.2f * zx;
    g_vyn[i] = vy + 0.2f * zy;
    g_m0[i]  = p[3];   // mass update is forced 0 -> mass = input mass
}

// ---------------- advection (semi-Lagrangian, periodic bilinear) ----------------
__global__ void advect_kernel(const float* __restrict__ src, float* __restrict__ dst){
    int i = blockIdx.x * blockDim.x + threadIdx.x;
    int x = i & (W-1);
    int y = (i >> 9) & (H-1);
    int b = i >> 18;
    float vx = g_vxn[i], vy = g_vyn[i];
    float sy = (float)y - vy * 0.25f;
    float sx = (float)x - vx * 0.25f;
    float y0f = floorf(sy), x0f = floorf(sx);
    float fy = sy - y0f, fx = sx - x0f;
    int y0 = ((int)y0f) & (H-1);
    int x0 = ((int)x0f) & (W-1);
    int y1 = (y0 + 1) & (H-1);
    int x1 = (x0 + 1) & (W-1);
    int base = b << 18;
    float m00 = __ldg(&src[base + (y0<<9) + x0]);
    float m01 = __ldg(&src[base + (y0<<9) + x1]);
    float m10 = __ldg(&src[base + (y1<<9) + x0]);
    float m11 = __ldg(&src[base + (y1<<9) + x1]);
    dst[i] = (1.0f - fy) * ((1.0f - fx) * m00 + fx * m01)
           +         fy  * ((1.0f - fx) * m10 + fx * m11);
}

// ---------------- diffuse + write mass channel ----------------
__global__ void diffuse_kernel(const float* __restrict__ mb, float* __restrict__ O){
    int i = blockIdx.x * blockDim.x + threadIdx.x;
    int x = i & (W-1);
    int y = (i >> 9) & (H-1);
    int b = i >> 18;
    int xm = (x-1)&(W-1), xp = (x+1)&(W-1);
    int ym = (y-1)&(H-1), yp = (y+1)&(H-1);
    int base = b << 18;
    float mc  = mb[i];
    // order matches JAX: right + left + down + up
    float avg = (__ldg(&mb[base + (y<<9)  + xp])
               + __ldg(&mb[base + (y<<9)  + xm])
               + __ldg(&mb[base + (yp<<9) + x ])
               + __ldg(&mb[base + (ym<<9) + x ])) / 4.0f;
    O[(size_t)i * 16 + 3] = mc + 0.05f * (avg - mc);
}

// ---------------- launch ----------------
extern "C" void kernel_launch(void* const* d_in, const int* in_sizes, int n_in,
                              void* d_out, int out_size){
    const float* state = (const float*)d_in[0];
    const int*   seed  = (const int*)d_in[1];

    cudaMemcpyToSymbolAsync(cw1,   d_in[2],  sizeof(float)*64*64, 0, cudaMemcpyDeviceToDevice, 0);
    cudaMemcpyToSymbolAsync(cb1,   d_in[3],  sizeof(float)*64,    0, cudaMemcpyDeviceToDevice, 0);
    cudaMemcpyToSymbolAsync(cw2,   d_in[4],  sizeof(float)*64*32, 0, cudaMemcpyDeviceToDevice, 0);
    cudaMemcpyToSymbolAsync(cb2,   d_in[5],  sizeof(float)*32,    0, cudaMemcpyDeviceToDevice, 0);
    cudaMemcpyToSymbolAsync(cwrgb, d_in[6],  sizeof(float)*96,    0, cudaMemcpyDeviceToDevice, 0);
    cudaMemcpyToSymbolAsync(cbrgb, d_in[7],  sizeof(float)*3,     0, cudaMemcpyDeviceToDevice, 0);
    cudaMemcpyToSymbolAsync(cwvel, d_in[8],  sizeof(float)*64,    0, cudaMemcpyDeviceToDevice, 0);
    cudaMemcpyToSymbolAsync(cbvel, d_in[9],  sizeof(float)*2,     0, cudaMemcpyDeviceToDevice, 0);
    cudaMemcpyToSymbolAsync(cwhid, d_in[10], sizeof(float)*256,   0, cudaMemcpyDeviceToDevice, 0);
    cudaMemcpyToSymbolAsync(cbhid, d_in[11], sizeof(float)*8,     0, cudaMemcpyDeviceToDevice, 0);

    key_setup<<<1, 1>>>(seed);

    float *m0, *m1;
    cudaGetSymbolAddress((void**)&m0, g_m0);
    cudaGetSymbolAddress((void**)&m1, g_m1);

    nca_kernel<<<NPIX/128, 128>>>(state, (float*)d_out);
    advect_kernel<<<NPIX/256, 256>>>(m0, m1);
    advect_kernel<<<NPIX/256, 256>>>(m1, m0);
    diffuse_kernel<<<NPIX/256, 256>>>(m0, (float*)d_out);
}

// round 6
// speedup vs baseline: 1.1249x; 1.1249x over previous
#include <cuda_runtime.h>
#include <cstdint>
#include <math.h>

// ---------------- constants -----------------
#define H 512
#define W 512
#define B 8
#define NPIX (B*H*W)          // 2097152

typedef unsigned long long ull;

__constant__ float cw1[64*64];
__constant__ float cb1[64];
__constant__ float cw2[64*32];
__constant__ float cb2[32];
__constant__ float cwrgb[32*3];
__constant__ float cbrgb[3];
__constant__ float cwvel[32*2];
__constant__ float cbvel[2];
__constant__ float cwhid[32*8];
__constant__ float cbhid[8];

// scratch (static device memory: allowed; no allocation)
__device__ float g_vxn[NPIX];
__device__ float g_vyn[NPIX];
__device__ float g_m0[NPIX];
__device__ float g_m1[NPIX];
__device__ unsigned int g_keys[6];

// ---------------- packed f32x2 helpers -----------------
__device__ __forceinline__ ull pack2(float lo, float hi){
    ull r; asm("mov.b64 %0, {%1, %2};" : "=l"(r) : "f"(lo), "f"(hi)); return r;
}
__device__ __forceinline__ void unpack2(ull v, float& lo, float& hi){
    asm("mov.b64 {%0, %1}, %2;" : "=f"(lo), "=f"(hi) : "l"(v));
}
__device__ __forceinline__ ull ffma2(ull a, ull b, ull c){
    ull d; asm("fma.rn.f32x2 %0, %1, %2, %3;" : "=l"(d) : "l"(a), "l"(b), "l"(c)); return d;
}
__device__ __forceinline__ ull fmul2(ull a, ull b){
    ull d; asm("mul.rn.f32x2 %0, %1, %2;" : "=l"(d) : "l"(a), "l"(b)); return d;
}

// ---------------- threefry2x32 (bit-exact JAX, partitionable) -----------------
__device__ __forceinline__ uint32_t rotl32(uint32_t v, int r){ return (v<<r)|(v>>(32-r)); }

__device__ __forceinline__ void tf2x32(uint32_t k0, uint32_t k1, uint32_t x0, uint32_t x1,
                                       uint32_t& o0, uint32_t& o1){
    uint32_t k2 = k0 ^ k1 ^ 0x1BD11BDAu;
    x0 += k0; x1 += k1;
#define TFR(r) { x0 += x1; x1 = rotl32(x1,(r)); x1 ^= x0; }
    TFR(13) TFR(15) TFR(26) TFR(6)   x0 += k1; x1 += k2 + 1u;
    TFR(17) TFR(29) TFR(16) TFR(24)  x0 += k2; x1 += k0 + 2u;
    TFR(13) TFR(15) TFR(26) TFR(6)   x0 += k0; x1 += k1 + 3u;
    TFR(17) TFR(29) TFR(16) TFR(24)  x0 += k1; x1 += k2 + 4u;
    TFR(13) TFR(15) TFR(26) TFR(6)   x0 += k2; x1 += k0 + 5u;
#undef TFR
    o0 = x0; o1 = x1;
}

// partitionable random_bits: counter (0, i), output = o0 ^ o1
__device__ __forceinline__ uint32_t rng_bits(uint32_t k0, uint32_t k1, uint32_t i){
    uint32_t o0, o1;
    tf2x32(k0, k1, 0u, i, o0, o1);
    return o0 ^ o1;
}

__device__ __forceinline__ float bits_to_u01(uint32_t b){
    return __uint_as_float((b >> 9) | 0x3f800000u) - 1.0f;
}

// XLA ErfInv (f32, Giles polynomial)
__device__ __forceinline__ float erfinv32(float x){
    float w = -log1pf(-x*x);
    float p;
    if (w < 5.0f){
        w -= 2.5f;
        p = 2.81022636e-08f;
        p = fmaf(p, w, 3.43273939e-07f);
        p = fmaf(p, w, -3.5233877e-06f);
        p = fmaf(p, w, -4.39150654e-06f);
        p = fmaf(p, w, 0.00021858087f);
        p = fmaf(p, w, -0.00125372503f);
        p = fmaf(p, w, -0.00417768164f);
        p = fmaf(p, w, 0.246640727f);
        p = fmaf(p, w, 1.50140941f);
    } else {
        w = sqrtf(w) - 3.0f;
        p = -0.000200214257f;
        p = fmaf(p, w, 0.000100950558f);
        p = fmaf(p, w, 0.00134934322f);
        p = fmaf(p, w, -0.00367342844f);
        p = fmaf(p, w, 0.00573950773f);
        p = fmaf(p, w, -0.0076224613f);
        p = fmaf(p, w, 0.00943887047f);
        p = fmaf(p, w, 1.00167406f);
        p = fmaf(p, w, 2.83297682f);
    }
    return p * x;
}

// ---------------- key derivation (fold-like split, partitionable) ----------------
__global__ void key_setup(const int* __restrict__ seed){
    uint32_t K0 = 0u;
    uint32_t K1 = (uint32_t)(*seed);
    uint32_t nk0, nk1;
    tf2x32(K0, K1, 0u, 1u, nk0, nk1);
    uint32_t a0,a1,b0,b1;
    tf2x32(nk0, nk1, 0u, 0u, a0, a1);
    tf2x32(nk0, nk1, 0u, 1u, b0, b1);
    g_keys[0] = K0; g_keys[1] = K1;
    g_keys[2] = a0; g_keys[3] = a1;   // k1 (vx noise)
    g_keys[4] = b0; g_keys[5] = b1;   // k2 (vy noise)
}

// ---------------- main NCA kernel ----------------
__global__ __launch_bounds__(128)
void nca_kernel(const float* __restrict__ S, float* __restrict__ O){
    __shared__ float sb[64*128];   // activation spill: column-major, conflict-free
    const int tid = threadIdx.x;
    const int i   = blockIdx.x * 128 + tid;
    const int x   = i & (W-1);
    const int y   = (i >> 9) & (H-1);
    const int b   = i >> 18;

    const int xm = (x-1)&(W-1), xp = (x+1)&(W-1);
    const int ym = (y-1)&(H-1), yp = (y+1)&(H-1);
    const size_t rowb = ((size_t)b) << 18;
    const float4* S4 = (const float4*)S;

#define PIXF4(yy,xx) ((rowb + (((size_t)(yy))<<9) + (size_t)(xx)) * 4)

    const ull one2  = pack2( 1.0f,  1.0f);
    const ull neg12 = pack2(-1.0f, -1.0f);
    const ull two2  = pack2( 2.0f,  2.0f);
    const ull neg22 = pack2(-2.0f, -2.0f);
    const ull neg42 = pack2(-4.0f, -4.0f);
    const ull eig2  = pack2(0.125f, 0.125f);
    const ull qtr2  = pack2(0.25f,  0.25f);

    // packed perception: pp[0..7]=s pairs, gx2[8], gy2[8], lap2[8]
    ull pp[8], gx2[8], gy2[8], lap2[8];
    {
        size_t a = PIXF4(y,x);
#pragma unroll
        for (int q = 0; q < 4; q++){
            float4 v = __ldg(&S4[a+q]);
            pp[2*q+0] = pack2(v.x, v.y);
            pp[2*q+1] = pack2(v.z, v.w);
        }
#pragma unroll
        for (int k = 0; k < 8; k++){
            gx2[k] = 0ull; gy2[k] = 0ull;
            lap2[k] = fmul2(neg42, pp[k]);
        }
    }

#define NBRP(yy,xx,STMT) { size_t a = PIXF4(yy,xx); ull v2[8]; \
    _Pragma("unroll") for (int q = 0; q < 4; q++){ \
        float4 vv = __ldg(&S4[a+q]); \
        v2[2*q+0] = pack2(vv.x, vv.y); v2[2*q+1] = pack2(vv.z, vv.w); } \
    _Pragma("unroll") for (int k = 0; k < 8; k++){ ull v = v2[k]; STMT; } }

    NBRP(ym, xm, { gx2[k] = ffma2(neg12, v, gx2[k]); gy2[k] = ffma2(neg12, v, gy2[k]); })
    NBRP(ym, x , { gy2[k] = ffma2(neg22, v, gy2[k]); lap2[k] = ffma2(one2, v, lap2[k]); })
    NBRP(ym, xp, { gx2[k] = ffma2(one2 , v, gx2[k]); gy2[k] = ffma2(neg12, v, gy2[k]); })
    NBRP(y , xm, { gx2[k] = ffma2(neg22, v, gx2[k]); lap2[k] = ffma2(one2, v, lap2[k]); })
    NBRP(y , xp, { gx2[k] = ffma2(two2 , v, gx2[k]); lap2[k] = ffma2(one2, v, lap2[k]); })
    NBRP(yp, xm, { gx2[k] = ffma2(neg12, v, gx2[k]); gy2[k] = ffma2(one2 , v, gy2[k]); })
    NBRP(yp, x , { gy2[k] = ffma2(two2 , v, gy2[k]); lap2[k] = ffma2(one2, v, lap2[k]); })
    NBRP(yp, xp, { gx2[k] = ffma2(one2 , v, gx2[k]); gy2[k] = ffma2(one2 , v, gy2[k]); })
#undef NBRP

#pragma unroll
    for (int k = 0; k < 8; k++){
        gx2[k]  = fmul2(eig2, gx2[k]);
        gy2[k]  = fmul2(eig2, gy2[k]);
        lap2[k] = fmul2(qtr2, lap2[k]);
    }

    // spill perception (scalar column layout: conflict-free)
#pragma unroll
    for (int k = 0; k < 8; k++){
        float a0, a1;
        unpack2(pp[k],  a0, a1); sb[(2*k   )*128+tid]=a0; sb[(2*k+ 1)*128+tid]=a1;
        unpack2(gx2[k], a0, a1); sb[(16+2*k)*128+tid]=a0; sb[(17+2*k)*128+tid]=a1;
        unpack2(gy2[k], a0, a1); sb[(32+2*k)*128+tid]=a0; sb[(33+2*k)*128+tid]=a1;
        unpack2(lap2[k],a0, a1); sb[(48+2*k)*128+tid]=a0; sb[(49+2*k)*128+tid]=a1;
    }

    // ---- layer 1: h[64] = relu(p . w1 + b1), packed pairs ----
    ull h2[32];
    {
        const ull* cb1p = (const ull*)cb1;
#pragma unroll
        for (int d2 = 0; d2 < 32; d2++) h2[d2] = cb1p[d2];
    }
#pragma unroll 4
    for (int c = 0; c < 64; c++){
        float pc = sb[c*128 + tid];
        ull pc2 = pack2(pc, pc);
        const ull* wrow = (const ull*)(cw1 + c*64);
#pragma unroll
        for (int d2 = 0; d2 < 32; d2++)
            h2[d2] = ffma2(pc2, wrow[d2], h2[d2]);
    }
    // relu + store scalar
#pragma unroll
    for (int d2 = 0; d2 < 32; d2++){
        float lo, hi; unpack2(h2[d2], lo, hi);
        sb[(2*d2  )*128+tid] = fmaxf(lo, 0.0f);
        sb[(2*d2+1)*128+tid] = fmaxf(hi, 0.0f);
    }

    // ---- layer 2: xo[32] = relu(h . w2 + b2), packed pairs ----
    ull xo2[16];
    {
        const ull* cb2p = (const ull*)cb2;
#pragma unroll
        for (int d2 = 0; d2 < 16; d2++) xo2[d2] = cb2p[d2];
    }
#pragma unroll 4
    for (int c = 0; c < 64; c++){
        float hc = sb[c*128 + tid];
        ull hc2 = pack2(hc, hc);
        const ull* wrow = (const ull*)(cw2 + c*32);
#pragma unroll
        for (int d2 = 0; d2 < 16; d2++)
            xo2[d2] = ffma2(hc2, wrow[d2], xo2[d2]);
    }
    float xo[32];
#pragma unroll
    for (int d2 = 0; d2 < 16; d2++){
        float lo, hi; unpack2(xo2[d2], lo, hi);
        xo[2*d2]   = fmaxf(lo, 0.0f);
        xo[2*d2+1] = fmaxf(hi, 0.0f);
    }

    // ---- heads (hid packed, rgb/vel scalar) ----
    float r0 = cbrgb[0], r1 = cbrgb[1], r2 = cbrgb[2];
    float dvx = cbvel[0], dvy = cbvel[1];
    ull hid2[4];
    {
        const ull* cbh = (const ull*)cbhid;
#pragma unroll
        for (int j = 0; j < 4; j++) hid2[j] = cbh[j];
    }
#pragma unroll
    for (int c = 0; c < 32; c++){
        float xc = xo[c];
        ull xc2 = pack2(xc, xc);
        r0  = fmaf(xc, cwrgb[c*3+0], r0);
        r1  = fmaf(xc, cwrgb[c*3+1], r1);
        r2  = fmaf(xc, cwrgb[c*3+2], r2);
        dvx = fmaf(xc, cwvel[c*2+0], dvx);
        dvy = fmaf(xc, cwvel[c*2+1], dvy);
        const ull* wh = (const ull*)(cwhid + c*8);
#pragma unroll
        for (int j = 0; j < 4; j++) hid2[j] = ffma2(xc2, wh[j], hid2[j]);
    }
    float hid[8];
#pragma unroll
    for (int j = 0; j < 4; j++) unpack2(hid2[j], hid[2*j], hid[2*j+1]);

    // ---- RNG: fire mask + velocity noise ----
    uint32_t K0 = g_keys[0], K1 = g_keys[1];
    uint32_t A0 = g_keys[2], A1 = g_keys[3];
    uint32_t B0 = g_keys[4], B1 = g_keys[5];
    uint32_t ui = (uint32_t)i;

    float um = bits_to_u01(rng_bits(K0, K1, ui));
    float m  = (um < 0.5f) ? 1.0f : 0.0f;

    const float LO   = -0.99999994f;
    const float SPAN =  1.99999994f;
    float uxr = bits_to_u01(rng_bits(A0, A1, ui));
    float uyr = bits_to_u01(rng_bits(B0, B1, ui));
    float ux  = fmaxf(LO, uxr * SPAN + LO);
    float uy  = fmaxf(LO, uyr * SPAN + LO);
    float zx  = 1.41421356f * erfinv32(ux);
    float zy  = 1.41421356f * erfinv32(uy);

    // ---- state update (unpack center channels) ----
    float s[16];
#pragma unroll
    for (int k = 0; k < 8; k++) unpack2(pp[k], s[2*k], s[2*k+1]);

    float o0c = fminf(fmaxf(s[0] + r0*m, 0.0f), 1.0f);
    float o1c = fminf(fmaxf(s[1] + r1*m, 0.0f), 1.0f);
    float o2c = fminf(fmaxf(s[2] + r2*m, 0.0f), 1.0f);
    float vx  = 0.95f * fminf(fmaxf(s[4] + dvx*m, -1.0f), 1.0f);
    float vy  = 0.95f * fminf(fmaxf(s[5] + dvy*m, -1.0f), 1.0f);

    float4* O4 = (float4*)O;
    size_t ob = (size_t)i * 4;
    O4[ob+0] = make_float4(o0c, o1c, o2c, s[3]);  // ch3 overwritten by diffuse pass
    O4[ob+1] = make_float4(vx, vy, s[6], s[7]);
    O4[ob+2] = make_float4(s[8]  + hid[0]*m, s[9]  + hid[1]*m,
                           s[10] + hid[2]*m, s[11] + hid[3]*m);
    O4[ob+3] = make_float4(s[12] + hid[4]*m, s[13] + hid[5]*m,
                           s[14] + hid[6]*m, s[15] + hid[7]*m);

    g_vxn[i] = vx + 0.2f * zx;
    g_vyn[i] = vy + 0.2f * zy;
    g_m0[i]  = s[3];
}

// ---------------- advection (semi-Lagrangian, periodic bilinear) ----------------
__global__ void advect_kernel(const float* __restrict__ src, float* __restrict__ dst){
    int i = blockIdx.x * blockDim.x + threadIdx.x;
    int x = i & (W-1);
    int y = (i >> 9) & (H-1);
    int b = i >> 18;
    float vx = g_vxn[i], vy = g_vyn[i];
    float sy = (float)y - vy * 0.25f;
    float sx = (float)x - vx * 0.25f;
    float y0f = floorf(sy), x0f = floorf(sx);
    float fy = sy - y0f, fx = sx - x0f;
    int y0 = ((int)y0f) & (H-1);
    int x0 = ((int)x0f) & (W-1);
    int y1 = (y0 + 1) & (H-1);
    int x1 = (x0 + 1) & (W-1);
    int base = b << 18;
    float m00 = __ldg(&src[base + (y0<<9) + x0]);
    float m01 = __ldg(&src[base + (y0<<9) + x1]);
    float m10 = __ldg(&src[base + (y1<<9) + x0]);
    float m11 = __ldg(&src[base + (y1<<9) + x1]);
    dst[i] = (1.0f - fy) * ((1.0f - fx) * m00 + fx * m01)
           +         fy  * ((1.0f - fx) * m10 + fx * m11);
}

// ---------------- diffuse + write mass channel ----------------
__global__ void diffuse_kernel(const float* __restrict__ mb, float* __restrict__ O){
    int i = blockIdx.x * blockDim.x + threadIdx.x;
    int x = i & (W-1);
    int y = (i >> 9) & (H-1);
    int b = i >> 18;
    int xm = (x-1)&(W-1), xp = (x+1)&(W-1);
    int ym = (y-1)&(H-1), yp = (y+1)&(H-1);
    int base = b << 18;
    float mc  = mb[i];
    float avg = (__ldg(&mb[base + (y<<9)  + xp])
               + __ldg(&mb[base + (y<<9)  + xm])
               + __ldg(&mb[base + (yp<<9) + x ])
               + __ldg(&mb[base + (ym<<9) + x ])) / 4.0f;
    O[(size_t)i * 16 + 3] = mc + 0.05f * (avg - mc);
}

// ---------------- launch ----------------
extern "C" void kernel_launch(void* const* d_in, const int* in_sizes, int n_in,
                              void* d_out, int out_size){
    const float* state = (const float*)d_in[0];
    const int*   seed  = (const int*)d_in[1];

    cudaMemcpyToSymbolAsync(cw1,   d_in[2],  sizeof(float)*64*64, 0, cudaMemcpyDeviceToDevice, 0);
    cudaMemcpyToSymbolAsync(cb1,   d_in[3],  sizeof(float)*64,    0, cudaMemcpyDeviceToDevice, 0);
    cudaMemcpyToSymbolAsync(cw2,   d_in[4],  sizeof(float)*64*32, 0, cudaMemcpyDeviceToDevice, 0);
    cudaMemcpyToSymbolAsync(cb2,   d_in[5],  sizeof(float)*32,    0, cudaMemcpyDeviceToDevice, 0);
    cudaMemcpyToSymbolAsync(cwrgb, d_in[6],  sizeof(float)*96,    0, cudaMemcpyDeviceToDevice, 0);
    cudaMemcpyToSymbolAsync(cbrgb, d_in[7],  sizeof(float)*3,     0, cudaMemcpyDeviceToDevice, 0);
    cudaMemcpyToSymbolAsync(cwvel, d_in[8],  sizeof(float)*64,    0, cudaMemcpyDeviceToDevice, 0);
    cudaMemcpyToSymbolAsync(cbvel, d_in[9],  sizeof(float)*2,     0, cudaMemcpyDeviceToDevice, 0);
    cudaMemcpyToSymbolAsync(cwhid, d_in[10], sizeof(float)*256,   0, cudaMemcpyDeviceToDevice, 0);
    cudaMemcpyToSymbolAsync(cbhid, d_in[11], sizeof(float)*8,     0, cudaMemcpyDeviceToDevice, 0);

    key_setup<<<1, 1>>>(seed);

    float *m0, *m1;
    cudaGetSymbolAddress((void**)&m0, g_m0);
    cudaGetSymbolAddress((void**)&m1, g_m1);

    nca_kernel<<<NPIX/128, 128>>>(state, (float*)d_out);
    advect_kernel<<<NPIX/256, 256>>>(m0, m1);
    advect_kernel<<<NPIX/256, 256>>>(m1, m0);
    diffuse_kernel<<<NPIX/256, 256>>>(m0, (float*)d_out);
}

// round 7
// speedup vs baseline: 1.7632x; 1.5674x over previous
#include <cuda_runtime.h>
#include <cstdint>
#include <math.h>

// ---------------- constants -----------------
#define H 512
#define W 512
#define B 8
#define NPIX (B*H*W)          // 2097152

typedef unsigned long long ull;

__constant__ float cw1[64*64];
__constant__ float cb1[64];
__constant__ float cw2[64*32];
__constant__ float cb2[32];
__constant__ float cwrgb[32*3];
__constant__ float cbrgb[3];
__constant__ float cwvel[32*2];
__constant__ float cbvel[2];
__constant__ float cwhid[32*8];
__constant__ float cbhid[8];

// scratch (static device memory: allowed; no allocation)
__device__ float g_vxn[NPIX];
__device__ float g_vyn[NPIX];
__device__ float g_m0[NPIX];
__device__ float g_m1[NPIX];
__device__ int   g_list[NPIX];
__device__ int   g_count;
__device__ unsigned int g_keys[6];

// ---------------- packed f32x2 helpers -----------------
__device__ __forceinline__ ull pack2(float lo, float hi){
    ull r; asm("mov.b64 %0, {%1, %2};" : "=l"(r) : "f"(lo), "f"(hi)); return r;
}
__device__ __forceinline__ void unpack2(ull v, float& lo, float& hi){
    asm("mov.b64 {%0, %1}, %2;" : "=f"(lo), "=f"(hi) : "l"(v));
}
__device__ __forceinline__ ull ffma2(ull a, ull b, ull c){
    ull d; asm("fma.rn.f32x2 %0, %1, %2, %3;" : "=l"(d) : "l"(a), "l"(b), "l"(c)); return d;
}
__device__ __forceinline__ ull fmul2(ull a, ull b){
    ull d; asm("mul.rn.f32x2 %0, %1, %2;" : "=l"(d) : "l"(a), "l"(b)); return d;
}

// ---------------- threefry2x32 (bit-exact JAX, partitionable) -----------------
__device__ __forceinline__ uint32_t rotl32(uint32_t v, int r){ return (v<<r)|(v>>(32-r)); }

__device__ __forceinline__ void tf2x32(uint32_t k0, uint32_t k1, uint32_t x0, uint32_t x1,
                                       uint32_t& o0, uint32_t& o1){
    uint32_t k2 = k0 ^ k1 ^ 0x1BD11BDAu;
    x0 += k0; x1 += k1;
#define TFR(r) { x0 += x1; x1 = rotl32(x1,(r)); x1 ^= x0; }
    TFR(13) TFR(15) TFR(26) TFR(6)   x0 += k1; x1 += k2 + 1u;
    TFR(17) TFR(29) TFR(16) TFR(24)  x0 += k2; x1 += k0 + 2u;
    TFR(13) TFR(15) TFR(26) TFR(6)   x0 += k0; x1 += k1 + 3u;
    TFR(17) TFR(29) TFR(16) TFR(24)  x0 += k1; x1 += k2 + 4u;
    TFR(13) TFR(15) TFR(26) TFR(6)   x0 += k2; x1 += k0 + 5u;
#undef TFR
    o0 = x0; o1 = x1;
}

// partitionable random_bits: counter (0, i), output = o0 ^ o1
__device__ __forceinline__ uint32_t rng_bits(uint32_t k0, uint32_t k1, uint32_t i){
    uint32_t o0, o1;
    tf2x32(k0, k1, 0u, i, o0, o1);
    return o0 ^ o1;
}

__device__ __forceinline__ float bits_to_u01(uint32_t b){
    return __uint_as_float((b >> 9) | 0x3f800000u) - 1.0f;
}

// XLA ErfInv (f32, Giles polynomial)
__device__ __forceinline__ float erfinv32(float x){
    float w = -log1pf(-x*x);
    float p;
    if (w < 5.0f){
        w -= 2.5f;
        p = 2.81022636e-08f;
        p = fmaf(p, w, 3.43273939e-07f);
        p = fmaf(p, w, -3.5233877e-06f);
        p = fmaf(p, w, -4.39150654e-06f);
        p = fmaf(p, w, 0.00021858087f);
        p = fmaf(p, w, -0.00125372503f);
        p = fmaf(p, w, -0.00417768164f);
        p = fmaf(p, w, 0.246640727f);
        p = fmaf(p, w, 1.50140941f);
    } else {
        w = sqrtf(w) - 3.0f;
        p = -0.000200214257f;
        p = fmaf(p, w, 0.000100950558f);
        p = fmaf(p, w, 0.00134934322f);
        p = fmaf(p, w, -0.00367342844f);
        p = fmaf(p, w, 0.00573950773f);
        p = fmaf(p, w, -0.0076224613f);
        p = fmaf(p, w, 0.00943887047f);
        p = fmaf(p, w, 1.00167406f);
        p = fmaf(p, w, 2.83297682f);
    }
    return p * x;
}

// ---------------- key derivation (fold-like split, partitionable) ----------------
__global__ void key_setup(const int* __restrict__ seed){
    uint32_t K0 = 0u;
    uint32_t K1 = (uint32_t)(*seed);
    uint32_t nk0, nk1;
    tf2x32(K0, K1, 0u, 1u, nk0, nk1);
    uint32_t a0,a1,b0,b1;
    tf2x32(nk0, nk1, 0u, 0u, a0, a1);
    tf2x32(nk0, nk1, 0u, 1u, b0, b1);
    g_keys[0] = K0; g_keys[1] = K1;
    g_keys[2] = a0; g_keys[3] = a1;   // k1 (vx noise)
    g_keys[4] = b0; g_keys[5] = b1;   // k2 (vy noise)
    g_count = 0;                      // reset compaction counter each replay
}

// ---------------- kernel A: mask + noise + unfired fast path + compaction ----------------
__global__ __launch_bounds__(256)
void mask_kernel(const float* __restrict__ S, float* __restrict__ O){
    const int i    = blockIdx.x * 256 + threadIdx.x;
    const int lane = threadIdx.x & 31;

    uint32_t K0 = g_keys[0], K1 = g_keys[1];
    uint32_t A0 = g_keys[2], A1 = g_keys[3];
    uint32_t B0 = g_keys[4], B1 = g_keys[5];
    uint32_t ui = (uint32_t)i;

    float um = bits_to_u01(rng_bits(K0, K1, ui));
    int fired = (um < 0.5f);

    const float LO   = -0.99999994f;
    const float SPAN =  1.99999994f;
    float uxr = bits_to_u01(rng_bits(A0, A1, ui));
    float uyr = bits_to_u01(rng_bits(B0, B1, ui));
    float ux  = fmaxf(LO, uxr * SPAN + LO);
    float uy  = fmaxf(LO, uyr * SPAN + LO);
    float zx  = 1.41421356f * erfinv32(ux);
    float zy  = 1.41421356f * erfinv32(uy);

    // center pixel load
    const float4* S4 = (const float4*)S;
    size_t a = (size_t)i * 4;
    float4 v0 = __ldg(&S4[a+0]);
    float4 v1 = __ldg(&S4[a+1]);
    float4 v2 = __ldg(&S4[a+2]);
    float4 v3 = __ldg(&S4[a+3]);

    g_m0[i] = v0.w;   // mass channel (update forced 0)

    if (fired){
        // stash raw noise; kernel B finishes velocity
        g_vxn[i] = zx;
        g_vyn[i] = zy;
    } else {
        // full unfired output: ds contributes nothing
        float o0c = fminf(fmaxf(v0.x, 0.0f), 1.0f);
        float o1c = fminf(fmaxf(v0.y, 0.0f), 1.0f);
        float o2c = fminf(fmaxf(v0.z, 0.0f), 1.0f);
        float vx  = 0.95f * fminf(fmaxf(v1.x, -1.0f), 1.0f);
        float vy  = 0.95f * fminf(fmaxf(v1.y, -1.0f), 1.0f);

        float4* O4 = (float4*)O;
        size_t ob = (size_t)i * 4;
        O4[ob+0] = make_float4(o0c, o1c, o2c, v0.w);  // ch3 overwritten by diffuse
        O4[ob+1] = make_float4(vx, vy, v1.z, v1.w);
        O4[ob+2] = v2;
        O4[ob+3] = v3;

        g_vxn[i] = vx + 0.2f * zx;
        g_vyn[i] = vy + 0.2f * zy;
    }

    // warp-level compaction of fired indices
    unsigned bal = __ballot_sync(0xffffffffu, fired);
    int rank = __popc(bal & ((1u << lane) - 1u));
    int cnt  = __popc(bal);
    int base = 0;
    if (lane == 0 && cnt) base = atomicAdd(&g_count, cnt);
    base = __shfl_sync(0xffffffffu, base, 0);
    if (fired) g_list[base + rank] = i;
}

// ---------------- kernel B: full MLP for fired pixels only ----------------
__global__ __launch_bounds__(128)
void nca_fired_kernel(const float* __restrict__ S, float* __restrict__ O){
    __shared__ float sb[64*128];   // activation spill: column-major, conflict-free
    const int tid = threadIdx.x;
    const int j   = blockIdx.x * 128 + tid;
    if (j >= g_count) return;      // no barriers in this kernel -> safe early exit
    const int i   = g_list[j];
    const int x   = i & (W-1);
    const int y   = (i >> 9) & (H-1);
    const int b   = i >> 18;

    const int xm = (x-1)&(W-1), xp = (x+1)&(W-1);
    const int ym = (y-1)&(H-1), yp = (y+1)&(H-1);
    const size_t rowb = ((size_t)b) << 18;
    const float4* S4 = (const float4*)S;

#define PIXF4(yy,xx) ((rowb + (((size_t)(yy))<<9) + (size_t)(xx)) * 4)

    const ull one2  = pack2( 1.0f,  1.0f);
    const ull neg12 = pack2(-1.0f, -1.0f);
    const ull two2  = pack2( 2.0f,  2.0f);
    const ull neg22 = pack2(-2.0f, -2.0f);
    const ull neg42 = pack2(-4.0f, -4.0f);
    const ull eig2  = pack2(0.125f, 0.125f);
    const ull qtr2  = pack2(0.25f,  0.25f);

    // packed perception: pp[0..7]=s pairs, gx2[8], gy2[8], lap2[8]
    ull pp[8], gx2[8], gy2[8], lap2[8];
    {
        size_t a = PIXF4(y,x);
#pragma unroll
        for (int q = 0; q < 4; q++){
            float4 v = __ldg(&S4[a+q]);
            pp[2*q+0] = pack2(v.x, v.y);
            pp[2*q+1] = pack2(v.z, v.w);
        }
#pragma unroll
        for (int k = 0; k < 8; k++){
            gx2[k] = 0ull; gy2[k] = 0ull;
            lap2[k] = fmul2(neg42, pp[k]);
        }
    }

#define NBRP(yy,xx,STMT) { size_t a = PIXF4(yy,xx); ull v2[8]; \
    _Pragma("unroll") for (int q = 0; q < 4; q++){ \
        float4 vv = __ldg(&S4[a+q]); \
        v2[2*q+0] = pack2(vv.x, vv.y); v2[2*q+1] = pack2(vv.z, vv.w); } \
    _Pragma("unroll") for (int k = 0; k < 8; k++){ ull v = v2[k]; STMT; } }

    NBRP(ym, xm, { gx2[k] = ffma2(neg12, v, gx2[k]); gy2[k] = ffma2(neg12, v, gy2[k]); })
    NBRP(ym, x , { gy2[k] = ffma2(neg22, v, gy2[k]); lap2[k] = ffma2(one2, v, lap2[k]); })
    NBRP(ym, xp, { gx2[k] = ffma2(one2 , v, gx2[k]); gy2[k] = ffma2(neg12, v, gy2[k]); })
    NBRP(y , xm, { gx2[k] = ffma2(neg22, v, gx2[k]); lap2[k] = ffma2(one2, v, lap2[k]); })
    NBRP(y , xp, { gx2[k] = ffma2(two2 , v, gx2[k]); lap2[k] = ffma2(one2, v, lap2[k]); })
    NBRP(yp, xm, { gx2[k] = ffma2(neg12, v, gx2[k]); gy2[k] = ffma2(one2 , v, gy2[k]); })
    NBRP(yp, x , { gy2[k] = ffma2(two2 , v, gy2[k]); lap2[k] = ffma2(one2, v, lap2[k]); })
    NBRP(yp, xp, { gx2[k] = ffma2(one2 , v, gx2[k]); gy2[k] = ffma2(one2 , v, gy2[k]); })
#undef NBRP

#pragma unroll
    for (int k = 0; k < 8; k++){
        gx2[k]  = fmul2(eig2, gx2[k]);
        gy2[k]  = fmul2(eig2, gy2[k]);
        lap2[k] = fmul2(qtr2, lap2[k]);
    }

    // spill perception (scalar column layout: conflict-free)
#pragma unroll
    for (int k = 0; k < 8; k++){
        float a0, a1;
        unpack2(pp[k],  a0, a1); sb[(2*k   )*128+tid]=a0; sb[(2*k+ 1)*128+tid]=a1;
        unpack2(gx2[k], a0, a1); sb[(16+2*k)*128+tid]=a0; sb[(17+2*k)*128+tid]=a1;
        unpack2(gy2[k], a0, a1); sb[(32+2*k)*128+tid]=a0; sb[(33+2*k)*128+tid]=a1;
        unpack2(lap2[k],a0, a1); sb[(48+2*k)*128+tid]=a0; sb[(49+2*k)*128+tid]=a1;
    }

    // ---- layer 1: h[64] = relu(p . w1 + b1), packed pairs ----
    ull h2[32];
    {
        const ull* cb1p = (const ull*)cb1;
#pragma unroll
        for (int d2 = 0; d2 < 32; d2++) h2[d2] = cb1p[d2];
    }
#pragma unroll 4
    for (int c = 0; c < 64; c++){
        float pc = sb[c*128 + tid];
        ull pc2 = pack2(pc, pc);
        const ull* wrow = (const ull*)(cw1 + c*64);
#pragma unroll
        for (int d2 = 0; d2 < 32; d2++)
            h2[d2] = ffma2(pc2, wrow[d2], h2[d2]);
    }
#pragma unroll
    for (int d2 = 0; d2 < 32; d2++){
        float lo, hi; unpack2(h2[d2], lo, hi);
        sb[(2*d2  )*128+tid] = fmaxf(lo, 0.0f);
        sb[(2*d2+1)*128+tid] = fmaxf(hi, 0.0f);
    }

    // ---- layer 2: xo[32] = relu(h . w2 + b2), packed pairs ----
    ull xo2[16];
    {
        const ull* cb2p = (const ull*)cb2;
#pragma unroll
        for (int d2 = 0; d2 < 16; d2++) xo2[d2] = cb2p[d2];
    }
#pragma unroll 4
    for (int c = 0; c < 64; c++){
        float hc = sb[c*128 + tid];
        ull hc2 = pack2(hc, hc);
        const ull* wrow = (const ull*)(cw2 + c*32);
#pragma unroll
        for (int d2 = 0; d2 < 16; d2++)
            xo2[d2] = ffma2(hc2, wrow[d2], xo2[d2]);
    }
    float xo[32];
#pragma unroll
    for (int d2 = 0; d2 < 16; d2++){
        float lo, hi; unpack2(xo2[d2], lo, hi);
        xo[2*d2]   = fmaxf(lo, 0.0f);
        xo[2*d2+1] = fmaxf(hi, 0.0f);
    }

    // ---- heads (hid packed, rgb/vel scalar) ----
    float r0 = cbrgb[0], r1 = cbrgb[1], r2 = cbrgb[2];
    float dvx = cbvel[0], dvy = cbvel[1];
    ull hid2[4];
    {
        const ull* cbh = (const ull*)cbhid;
#pragma unroll
        for (int jj = 0; jj < 4; jj++) hid2[jj] = cbh[jj];
    }
#pragma unroll
    for (int c = 0; c < 32; c++){
        float xc = xo[c];
        ull xc2 = pack2(xc, xc);
        r0  = fmaf(xc, cwrgb[c*3+0], r0);
        r1  = fmaf(xc, cwrgb[c*3+1], r1);
        r2  = fmaf(xc, cwrgb[c*3+2], r2);
        dvx = fmaf(xc, cwvel[c*2+0], dvx);
        dvy = fmaf(xc, cwvel[c*2+1], dvy);
        const ull* wh = (const ull*)(cwhid + c*8);
#pragma unroll
        for (int jj = 0; jj < 4; jj++) hid2[jj] = ffma2(xc2, wh[jj], hid2[jj]);
    }
    float hid[8];
#pragma unroll
    for (int jj = 0; jj < 4; jj++) unpack2(hid2[jj], hid[2*jj], hid[2*jj+1]);

    // ---- state update (m == 1 for all pixels here) ----
    float s[16];
#pragma unroll
    for (int k = 0; k < 8; k++) unpack2(pp[k], s[2*k], s[2*k+1]);

    float o0c = fminf(fmaxf(s[0] + r0, 0.0f), 1.0f);
    float o1c = fminf(fmaxf(s[1] + r1, 0.0f), 1.0f);
    float o2c = fminf(fmaxf(s[2] + r2, 0.0f), 1.0f);
    float vx  = 0.95f * fminf(fmaxf(s[4] + dvx, -1.0f), 1.0f);
    float vy  = 0.95f * fminf(fmaxf(s[5] + dvy, -1.0f), 1.0f);

    float4* O4 = (float4*)O;
    size_t ob = (size_t)i * 4;
    O4[ob+0] = make_float4(o0c, o1c, o2c, s[3]);  // ch3 overwritten by diffuse pass
    O4[ob+1] = make_float4(vx, vy, s[6], s[7]);
    O4[ob+2] = make_float4(s[8]  + hid[0], s[9]  + hid[1],
                           s[10] + hid[2], s[11] + hid[3]);
    O4[ob+3] = make_float4(s[12] + hid[4], s[13] + hid[5],
                           s[14] + hid[6], s[15] + hid[7]);

    // finish velocity: raw noise was stashed by kernel A
    float zx = g_vxn[i];
    float zy = g_vyn[i];
    g_vxn[i] = vx + 0.2f * zx;
    g_vyn[i] = vy + 0.2f * zy;
}

// ---------------- advection (semi-Lagrangian, periodic bilinear) ----------------
__global__ void advect_kernel(const float* __restrict__ src, float* __restrict__ dst){
    int i = blockIdx.x * blockDim.x + threadIdx.x;
    int x = i & (W-1);
    int y = (i >> 9) & (H-1);
    int b = i >> 18;
    float vx = g_vxn[i], vy = g_vyn[i];
    float sy = (float)y - vy * 0.25f;
    float sx = (float)x - vx * 0.25f;
    float y0f = floorf(sy), x0f = floorf(sx);
    float fy = sy - y0f, fx = sx - x0f;
    int y0 = ((int)y0f) & (H-1);
    int x0 = ((int)x0f) & (W-1);
    int y1 = (y0 + 1) & (H-1);
    int x1 = (x0 + 1) & (W-1);
    int base = b << 18;
    float m00 = __ldg(&src[base + (y0<<9) + x0]);
    float m01 = __ldg(&src[base + (y0<<9) + x1]);
    float m10 = __ldg(&src[base + (y1<<9) + x0]);
    float m11 = __ldg(&src[base + (y1<<9) + x1]);
    dst[i] = (1.0f - fy) * ((1.0f - fx) * m00 + fx * m01)
           +         fy  * ((1.0f - fx) * m10 + fx * m11);
}

// ---------------- diffuse + write mass channel ----------------
__global__ void diffuse_kernel(const float* __restrict__ mb, float* __restrict__ O){
    int i = blockIdx.x * blockDim.x + threadIdx.x;
    int x = i & (W-1);
    int y = (i >> 9) & (H-1);
    int b = i >> 18;
    int xm = (x-1)&(W-1), xp = (x+1)&(W-1);
    int ym = (y-1)&(H-1), yp = (y+1)&(H-1);
    int base = b << 18;
    float mc  = mb[i];
    float avg = (__ldg(&mb[base + (y<<9)  + xp])
               + __ldg(&mb[base + (y<<9)  + xm])
               + __ldg(&mb[base + (yp<<9) + x ])
               + __ldg(&mb[base + (ym<<9) + x ])) / 4.0f;
    O[(size_t)i * 16 + 3] = mc + 0.05f * (avg - mc);
}

// ---------------- launch ----------------
extern "C" void kernel_launch(void* const* d_in, const int* in_sizes, int n_in,
                              void* d_out, int out_size){
    const float* state = (const float*)d_in[0];
    const int*   seed  = (const int*)d_in[1];

    cudaMemcpyToSymbolAsync(cw1,   d_in[2],  sizeof(float)*64*64, 0, cudaMemcpyDeviceToDevice, 0);
    cudaMemcpyToSymbolAsync(cb1,   d_in[3],  sizeof(float)*64,    0, cudaMemcpyDeviceToDevice, 0);
    cudaMemcpyToSymbolAsync(cw2,   d_in[4],  sizeof(float)*64*32, 0, cudaMemcpyDeviceToDevice, 0);
    cudaMemcpyToSymbolAsync(cb2,   d_in[5],  sizeof(float)*32,    0, cudaMemcpyDeviceToDevice, 0);
    cudaMemcpyToSymbolAsync(cwrgb, d_in[6],  sizeof(float)*96,    0, cudaMemcpyDeviceToDevice, 0);
    cudaMemcpyToSymbolAsync(cbrgb, d_in[7],  sizeof(float)*3,     0, cudaMemcpyDeviceToDevice, 0);
    cudaMemcpyToSymbolAsync(cwvel, d_in[8],  sizeof(float)*64,    0, cudaMemcpyDeviceToDevice, 0);
    cudaMemcpyToSymbolAsync(cbvel, d_in[9],  sizeof(float)*2,     0, cudaMemcpyDeviceToDevice, 0);
    cudaMemcpyToSymbolAsync(cwhid, d_in[10], sizeof(float)*256,   0, cudaMemcpyDeviceToDevice, 0);
    cudaMemcpyToSymbolAsync(cbhid, d_in[11], sizeof(float)*8,     0, cudaMemcpyDeviceToDevice, 0);

    key_setup<<<1, 1>>>(seed);

    float *m0, *m1;
    cudaGetSymbolAddress((void**)&m0, g_m0);
    cudaGetSymbolAddress((void**)&m1, g_m1);

    mask_kernel<<<NPIX/256, 256>>>(state, (float*)d_out);
    nca_fired_kernel<<<NPIX/128, 128>>>(state, (float*)d_out);
    advect_kernel<<<NPIX/256, 256>>>(m0, m1);
    advect_kernel<<<NPIX/256, 256>>>(m1, m0);
    diffuse_kernel<<<NPIX/256, 256>>>(m0, (float*)d_out);
}